// round 7
// baseline (speedup 1.0000x reference)
#include <cuda_runtime.h>

#define BATCH   4
#define N1_PER  16384
#define N2_PER  4096
#define N1_TOT  (BATCH * N1_PER)
#define N2_TOT  (BATCH * N2_PER)
#define C_IN    512
#define C_OUT   256
#define BN_EPS  1e-5f
#define KTILE   2048

typedef unsigned long long ull;

__device__ float g_h2[N2_TOT * C_OUT];
__device__ float g_W1s[C_OUT * C_OUT];
__device__ float g_W2s[C_IN * C_OUT];
__device__ float g_b1s[C_OUT];
__device__ float g_b2s[C_OUT];
__device__ float g_w3[N1_TOT * 3];
__device__ int   g_i3[N1_TOT * 3];

// ---------------------------------------------------------------------------
// packed f32x2 helpers
// ---------------------------------------------------------------------------
__device__ __forceinline__ ull pack2(float lo, float hi) {
    ull r; asm("mov.b64 %0, {%1, %2};" : "=l"(r) : "f"(lo), "f"(hi)); return r;
}
__device__ __forceinline__ void unpack2(ull v, float& lo, float& hi) {
    asm("mov.b64 {%0, %1}, %2;" : "=f"(lo), "=f"(hi) : "l"(v));
}
__device__ __forceinline__ ull fma2(ull a, ull b, ull c) {
    ull r; asm("fma.rn.f32x2 %0, %1, %2, %3;" : "=l"(r) : "l"(a), "l"(b), "l"(c));
    return r;
}

// ---------------------------------------------------------------------------
// BN folding into weights/bias (W stored K-major [K][N])
// ---------------------------------------------------------------------------
__global__ void prep_weights(const float* __restrict__ W1, const float* __restrict__ b1,
                             const float* __restrict__ g1, const float* __restrict__ be1,
                             const float* __restrict__ m1, const float* __restrict__ v1,
                             const float* __restrict__ W2, const float* __restrict__ b2,
                             const float* __restrict__ g2, const float* __restrict__ be2,
                             const float* __restrict__ m2, const float* __restrict__ v2)
{
    int n = blockIdx.x;
    float s1 = g1[n] * rsqrtf(v1[n] + BN_EPS);
    float s2 = g2[n] * rsqrtf(v2[n] + BN_EPS);
    for (int k = threadIdx.x; k < C_OUT; k += blockDim.x)
        g_W1s[k * C_OUT + n] = W1[n * C_OUT + k] * s1;
    for (int k = threadIdx.x; k < C_IN; k += blockDim.x)
        g_W2s[k * C_OUT + n] = W2[n * C_IN + k] * s2;
    if (threadIdx.x == 0) {
        g_b1s[n] = (b1[n] - m1[n]) * s1 + be1[n];
        g_b2s[n] = (b2[n] - m2[n]) * s2 + be2[n];
    }
}

// ---------------------------------------------------------------------------
// SGEMM  C = relu(A[M,K] @ W[K,N] + bias[N]); 128x128 tile, BK=8,
// double-buffered smem, packed f32x2 accumulation (FFMA2).
// ---------------------------------------------------------------------------
template <int LAYER>
__global__ __launch_bounds__(256, 2)
void sgemm_bias_relu(const float* __restrict__ A, float* __restrict__ Cout,
                     int M, int K)
{
    const int N = C_OUT;
    const float* __restrict__ W    = (LAYER == 1) ? g_W1s : g_W2s;
    const float* __restrict__ bias = (LAYER == 1) ? g_b1s : g_b2s;
    float* __restrict__ C          = (LAYER == 1) ? Cout  : g_h2;

    __shared__ float As[2][8][128];
    __shared__ float Bs[2][8][128];

    const int tid = threadIdx.x;
    const int bx  = blockIdx.x;
    const int by  = blockIdx.y;
    const int tx  = tid & 15;
    const int ty  = tid >> 4;

    const int arow = tid >> 1;
    const int acol = (tid & 1) * 4;
    const int brow = tid >> 5;
    const int bcol = (tid & 31) * 4;

    const float* Abase = A + (size_t)(by * 128 + arow) * K + acol;
    const float* Wbase = W + (size_t)brow * N + bx * 128 + bcol;

    // acc2[i][j] holds output cols {2j, 2j+1} packed (j in 0..3 over 8 cols)
    ull acc2[8][4];
#pragma unroll
    for (int i = 0; i < 8; i++)
#pragma unroll
        for (int j = 0; j < 4; j++) acc2[i][j] = pack2(0.f, 0.f);

    {
        float4 av = *(const float4*)(Abase);
        float4 bv = *(const float4*)(Wbase);
        As[0][acol + 0][arow] = av.x;
        As[0][acol + 1][arow] = av.y;
        As[0][acol + 2][arow] = av.z;
        As[0][acol + 3][arow] = av.w;
        *(float4*)&Bs[0][brow][bcol] = bv;
    }
    __syncthreads();

    int buf = 0;
    for (int k0 = 8; k0 <= K; k0 += 8) {
        float4 av2, bv2;
        const bool more = (k0 < K);
        if (more) {
            av2 = *(const float4*)(Abase + k0);
            bv2 = *(const float4*)(Wbase + (size_t)k0 * N);
        }

#pragma unroll
        for (int kk = 0; kk < 8; kk++) {
            float4 a0 = *(const float4*)&As[buf][kk][ty * 4];
            float4 a1 = *(const float4*)&As[buf][kk][64 + ty * 4];
            float4 b0 = *(const float4*)&Bs[buf][kk][tx * 4];
            float4 b1 = *(const float4*)&Bs[buf][kk][64 + tx * 4];
            float a[8] = {a0.x, a0.y, a0.z, a0.w, a1.x, a1.y, a1.z, a1.w};
            ull bb[4] = {pack2(b0.x, b0.y), pack2(b0.z, b0.w),
                         pack2(b1.x, b1.y), pack2(b1.z, b1.w)};
#pragma unroll
            for (int i = 0; i < 8; i++) {
                ull ai = pack2(a[i], a[i]);
#pragma unroll
                for (int j = 0; j < 4; j++)
                    acc2[i][j] = fma2(ai, bb[j], acc2[i][j]);
            }
        }

        if (more) {
            int nb = buf ^ 1;
            As[nb][acol + 0][arow] = av2.x;
            As[nb][acol + 1][arow] = av2.y;
            As[nb][acol + 2][arow] = av2.z;
            As[nb][acol + 3][arow] = av2.w;
            *(float4*)&Bs[nb][brow][bcol] = bv2;
        }
        __syncthreads();
        buf ^= 1;
    }

    const int col0 = bx * 128 + tx * 4;
    const int col1 = col0 + 64;
    float4 biasA = *(const float4*)&bias[col0];
    float4 biasB = *(const float4*)&bias[col1];

#pragma unroll
    for (int i = 0; i < 8; i++) {
        int row = by * 128 + ((i < 4) ? (ty * 4 + i) : (64 + ty * 4 + i - 4));
        float* Crow = C + (size_t)row * N;
        float c0, c1, c2, c3, c4, c5, c6, c7;
        unpack2(acc2[i][0], c0, c1);
        unpack2(acc2[i][1], c2, c3);
        unpack2(acc2[i][2], c4, c5);
        unpack2(acc2[i][3], c6, c7);
        float4 v0, v1;
        v0.x = fmaxf(c0 + biasA.x, 0.f);
        v0.y = fmaxf(c1 + biasA.y, 0.f);
        v0.z = fmaxf(c2 + biasA.z, 0.f);
        v0.w = fmaxf(c3 + biasA.w, 0.f);
        v1.x = fmaxf(c4 + biasB.x, 0.f);
        v1.y = fmaxf(c5 + biasB.y, 0.f);
        v1.z = fmaxf(c6 + biasB.z, 0.f);
        v1.w = fmaxf(c7 + biasB.w, 0.f);
        *(float4*)&Crow[col0] = v0;
        *(float4*)&Crow[col1] = v1;
    }
}

// ---------------------------------------------------------------------------
// top-3 update (caller guarantees d < d2)
// ---------------------------------------------------------------------------
__device__ __forceinline__ void upd3(float d, int j,
                                     float& d0, float& d1, float& d2,
                                     int& i0, int& i1, int& i2)
{
    if (d < d1) {
        d2 = d1; i2 = i1;
        if (d < d0) { d1 = d0; i1 = i0; d0 = d; i0 = j; }
        else        { d1 = d;  i1 = j; }
    } else { d2 = d; i2 = j; }
}

// ---------------------------------------------------------------------------
// 3-NN search. 2 queries per thread, 64 threads/block, 512 blocks.
// Ranking key r = |s|^2 - 2 q.s (monotone in d^2). Groups of 8 points with
// a single FMNMX-reduced guard per query; slow path rescans register-resident
// r values. Exact d^2 recomputed from global p2 for the 3 winners (precision).
// smem per pair j: sA[j]=(x0,x1,y0,y1)  sB[j]=(z0,z1,w0,w1), w=|s|^2.
// ---------------------------------------------------------------------------
__global__ __launch_bounds__(64)
void knn_search(const float* __restrict__ p1, const float* __restrict__ p2)
{
    __shared__ float4 sA[KTILE / 2];   // 16 KB
    __shared__ float4 sB[KTILE / 2];   // 16 KB

    const int b    = blockIdx.x >> 7;        // 128 blocks per batch
    const int qblk = blockIdx.x & 127;
    const int tid  = threadIdx.x;

    // two queries per thread
    int   qg[2];
    ull   qxv[2], qyv[2], qzv[2];
    float qx[2], qy[2], qz[2];
#pragma unroll
    for (int u = 0; u < 2; u++) {
        int q = b * N1_PER + qblk * 128 + u * 64 + tid;
        qg[u] = q;
        float x = p1[q * 3 + 0];
        float y = p1[q * 3 + 1];
        float z = p1[q * 3 + 2];
        qx[u] = x; qy[u] = y; qz[u] = z;
        qxv[u] = pack2(-2.f * x, -2.f * x);
        qyv[u] = pack2(-2.f * y, -2.f * y);
        qzv[u] = pack2(-2.f * z, -2.f * z);
    }

    float d0[2] = {1e30f, 1e30f}, d1[2] = {1e30f, 1e30f}, d2[2] = {1e30f, 1e30f};
    int   i0[2] = {0, 0},         i1[2] = {0, 0},         i2[2] = {0, 0};

    for (int t = 0; t < N2_PER / KTILE; t++) {
        __syncthreads();
        const float* src = p2 + ((size_t)b * N2_PER + t * KTILE) * 3;
        for (int pt = tid; pt < KTILE; pt += 64) {
            float x = src[pt * 3 + 0];
            float y = src[pt * 3 + 1];
            float z = src[pt * 3 + 2];
            float w = fmaf(z, z, fmaf(y, y, x * x));
            int j = pt >> 1, h = pt & 1;
            float* a  = (float*)&sA[j];
            float* bb = (float*)&sB[j];
            a[h]      = x;
            a[2 + h]  = y;
            bb[h]     = z;
            bb[2 + h] = w;
        }
        __syncthreads();

        const int tbase = t * KTILE;
#pragma unroll 2
        for (int g = 0; g < KTILE / 8; g++) {     // 4 pairs = 8 points per group
            ull xs[4], ys[4], zs[4], ws[4];
#pragma unroll
            for (int p = 0; p < 4; p++) {
                float4 a = sA[g * 4 + p];
                float4 v = sB[g * 4 + p];
                xs[p] = pack2(a.x, a.y);
                ys[p] = pack2(a.z, a.w);
                zs[p] = pack2(v.x, v.y);
                ws[p] = pack2(v.z, v.w);
            }

            float r[2][8];
#pragma unroll
            for (int u = 0; u < 2; u++)
#pragma unroll
                for (int p = 0; p < 4; p++) {
                    ull rr = fma2(qzv[u], zs[p], ws[p]);
                    rr = fma2(qyv[u], ys[p], rr);
                    rr = fma2(qxv[u], xs[p], rr);
                    unpack2(rr, r[u][2 * p], r[u][2 * p + 1]);
                }

#pragma unroll
            for (int u = 0; u < 2; u++) {
                float m01 = fminf(r[u][0], r[u][1]);
                float m23 = fminf(r[u][2], r[u][3]);
                float m45 = fminf(r[u][4], r[u][5]);
                float m67 = fminf(r[u][6], r[u][7]);
                float m = fminf(fminf(m01, m23), fminf(m45, m67));
                if (m < d2[u]) {
                    const int base = tbase + g * 8;
#pragma unroll
                    for (int c = 0; c < 8; c++)
                        if (r[u][c] < d2[u])
                            upd3(r[u][c], base + c,
                                 d0[u], d1[u], d2[u], i0[u], i1[u], i2[u]);
                }
            }
        }
    }

    // exact distances for the 3 winners (kills the r-key cancellation error)
#pragma unroll
    for (int u = 0; u < 2; u++) {
        int idx[3] = {i0[u], i1[u], i2[u]};
        float w[3];
#pragma unroll
        for (int c = 0; c < 3; c++) {
            const float* s = p2 + ((size_t)b * N2_PER + idx[c]) * 3;
            float dx = qx[u] - s[0];
            float dy = qy[u] - s[1];
            float dz = qz[u] - s[2];
            float dd = fmaf(dz, dz, fmaf(dy, dy, dx * dx));
            float dist = sqrtf(fmaxf(dd, 1e-12f));
            w[c] = 1.f / (dist + 1e-8f);
        }
        float inv = 1.f / (w[0] + w[1] + w[2]);
        int q = qg[u];
        g_w3[q * 3 + 0] = w[0] * inv;
        g_w3[q * 3 + 1] = w[1] * inv;
        g_w3[q * 3 + 2] = w[2] * inv;
        g_i3[q * 3 + 0] = b * N2_PER + idx[0];
        g_i3[q * 3 + 1] = b * N2_PER + idx[1];
        g_i3[q * 3 + 2] = b * N2_PER + idx[2];
    }
}

// ---------------------------------------------------------------------------
// Gather + accumulate: out[q][:] += sum_k w_k * h2[idx_k][:]
// ---------------------------------------------------------------------------
__global__ __launch_bounds__(256)
void gather_add(float* __restrict__ out)
{
    const int gid = blockIdx.x * 256 + threadIdx.x;
    const int q   = gid >> 6;
    const int c4  = gid & 63;

    float w0 = g_w3[q * 3 + 0];
    float w1 = g_w3[q * 3 + 1];
    float w2 = g_w3[q * 3 + 2];
    int   r0 = g_i3[q * 3 + 0];
    int   r1 = g_i3[q * 3 + 1];
    int   r2 = g_i3[q * 3 + 2];

    float4 f0 = *(const float4*)(g_h2 + (size_t)r0 * C_OUT + c4 * 4);
    float4 f1 = *(const float4*)(g_h2 + (size_t)r1 * C_OUT + c4 * 4);
    float4 f2 = *(const float4*)(g_h2 + (size_t)r2 * C_OUT + c4 * 4);

    float4* op = (float4*)out + (size_t)q * 64 + c4;
    float4 o = *op;
    o.x += w0 * f0.x + w1 * f1.x + w2 * f2.x;
    o.y += w0 * f0.y + w1 * f1.y + w2 * f2.y;
    o.z += w0 * f0.z + w1 * f1.z + w2 * f2.z;
    o.w += w0 * f0.w + w1 * f1.w + w2 * f2.w;
    *op = o;
}

extern "C" void kernel_launch(void* const* d_in, const int* in_sizes, int n_in,
                              void* d_out, int out_size)
{
    const float* p1 = (const float*)d_in[0];
    const float* x1 = (const float*)d_in[1];
    const float* p2 = (const float*)d_in[2];
    const float* x2 = (const float*)d_in[3];

    prep_weights<<<C_OUT, 256>>>((const float*)d_in[4],  (const float*)d_in[5],
                                 (const float*)d_in[6],  (const float*)d_in[7],
                                 (const float*)d_in[8],  (const float*)d_in[9],
                                 (const float*)d_in[10], (const float*)d_in[11],
                                 (const float*)d_in[12], (const float*)d_in[13],
                                 (const float*)d_in[14], (const float*)d_in[15]);

    {   // h2 = relu(bn(x2 @ W2^T)) -> g_h2
        dim3 grid(C_OUT / 128, N2_TOT / 128);
        sgemm_bias_relu<2><<<grid, 256>>>(x2, nullptr, N2_TOT, C_IN);
    }
    {   // h1 = relu(bn(x1 @ W1^T)) -> d_out
        dim3 grid(C_OUT / 128, N1_TOT / 128);
        sgemm_bias_relu<1><<<grid, 256>>>(x1, (float*)d_out, N1_TOT, C_OUT);
    }
    knn_search<<<BATCH * (N1_PER / 128), 64>>>(p1, p2);
    gather_add<<<(N1_TOT * 64) / 256, 256>>>((float*)d_out);
}

// round 12
// speedup vs baseline: 1.2925x; 1.2925x over previous
#include <cuda_runtime.h>
#include <cuda_bf16.h>
#include <cstdint>

#define BATCH   4
#define N1_PER  16384
#define N2_PER  4096
#define N1_TOT  (BATCH * N1_PER)
#define N2_TOT  (BATCH * N2_PER)
#define C_IN    512
#define C_OUT   256
#define BN_EPS  1e-5f
#define KT      4096

typedef unsigned long long ull;

// ---------------------------------------------------------------------------
// device-global scratch
// ---------------------------------------------------------------------------
__device__ float         g_h2[N2_TOT * C_OUT];
__device__ __nv_bfloat16 g_W1h[C_OUT * C_OUT];
__device__ __nv_bfloat16 g_W1l[C_OUT * C_OUT];
__device__ __nv_bfloat16 g_W2h[C_OUT * C_IN];
__device__ __nv_bfloat16 g_W2l[C_OUT * C_IN];
__device__ float         g_b1s[C_OUT];
__device__ float         g_b2s[C_OUT];
__device__ float         g_w3[N1_TOT * 3];
__device__ int           g_i3[N1_TOT * 3];

// ---------------------------------------------------------------------------
// helpers
// ---------------------------------------------------------------------------
__device__ __forceinline__ uint32_t smem_u32(const void* p) {
    uint32_t a;
    asm("{ .reg .u64 t; cvta.to.shared.u64 t, %1; cvt.u32.u64 %0, t; }"
        : "=r"(a) : "l"(p));
    return a;
}
__device__ __forceinline__ ull pack2(float lo, float hi) {
    ull r; asm("mov.b64 %0, {%1, %2};" : "=l"(r) : "f"(lo), "f"(hi)); return r;
}
__device__ __forceinline__ void unpack2(ull v, float& lo, float& hi) {
    asm("mov.b64 {%0, %1}, %2;" : "=f"(lo), "=f"(hi) : "l"(v));
}
__device__ __forceinline__ ull fma2(ull a, ull b, ull c) {
    ull r; asm("fma.rn.f32x2 %0, %1, %2, %3;" : "=l"(r) : "l"(a), "l"(b), "l"(c));
    return r;
}
__device__ __forceinline__ ull add2(ull a, ull b) {
    ull r; asm("add.rn.f32x2 %0, %1, %2;" : "=l"(r) : "l"(a), "l"(b)); return r;
}
__device__ __forceinline__ ull mul2(ull a, ull b) {
    ull r; asm("mul.rn.f32x2 %0, %1, %2;" : "=l"(r) : "l"(a), "l"(b)); return r;
}

// SW128 swizzle (Swizzle<3,4,3>)
__device__ __forceinline__ uint32_t sw128(uint32_t off) {
    return off ^ ((off >> 3) & 0x70);
}

#define LDSM4(r0, r1, r2, r3, addr) \
    asm volatile("ldmatrix.sync.aligned.m8n8.x4.shared.b16 {%0,%1,%2,%3}, [%4];" \
                 : "=r"(r0), "=r"(r1), "=r"(r2), "=r"(r3) : "r"(addr))

#define MMA_BF16(d, a0, a1, a2, a3, b0, b1) \
    asm volatile("mma.sync.aligned.m16n8k16.row.col.f32.bf16.bf16.f32 " \
                 "{%0,%1,%2,%3}, {%4,%5,%6,%7}, {%8,%9}, {%0,%1,%2,%3};" \
                 : "+f"((d)[0]), "+f"((d)[1]), "+f"((d)[2]), "+f"((d)[3]) \
                 : "r"(a0), "r"(a1), "r"(a2), "r"(a3), "r"(b0), "r"(b1))

// ---------------------------------------------------------------------------
// prep: fold BN into weights, split into bf16 hi/lo ([N][K] row-major)
// hi = truncate-to-bf16 (mask), lo = rn-bf16(residual)
// ---------------------------------------------------------------------------
__global__ void prep_weights(const float* __restrict__ W1, const float* __restrict__ b1,
                             const float* __restrict__ g1, const float* __restrict__ be1,
                             const float* __restrict__ m1, const float* __restrict__ v1,
                             const float* __restrict__ W2, const float* __restrict__ b2,
                             const float* __restrict__ g2, const float* __restrict__ be2,
                             const float* __restrict__ m2, const float* __restrict__ v2)
{
    int n = blockIdx.x;
    float s1 = g1[n] * rsqrtf(v1[n] + BN_EPS);
    float s2 = g2[n] * rsqrtf(v2[n] + BN_EPS);
    for (int k = threadIdx.x; k < C_OUT; k += blockDim.x) {
        float w = W1[n * C_OUT + k] * s1;
        uint32_t hb = __float_as_uint(w) & 0xFFFF0000u;
        float hf = __uint_as_float(hb);
        g_W1h[n * C_OUT + k] = __ushort_as_bfloat16((unsigned short)(hb >> 16));
        g_W1l[n * C_OUT + k] = __float2bfloat16(w - hf);
    }
    for (int k = threadIdx.x; k < C_IN; k += blockDim.x) {
        float w = W2[n * C_IN + k] * s2;
        uint32_t hb = __float_as_uint(w) & 0xFFFF0000u;
        float hf = __uint_as_float(hb);
        g_W2h[n * C_IN + k] = __ushort_as_bfloat16((unsigned short)(hb >> 16));
        g_W2l[n * C_IN + k] = __float2bfloat16(w - hf);
    }
    if (threadIdx.x == 0) {
        g_b1s[n] = (b1[n] - m1[n]) * s1 + be1[n];
        g_b2s[n] = (b2[n] - m2[n]) * s2 + be2[n];
    }
}

// ---------------------------------------------------------------------------
// mma.sync bf16 GEMM: C = relu(A[M,KTOT] @ W^T + bias), 3-term hi/lo split.
// CTA tile 128x128 (grid: x = N/128, y = M/128), 256 thr = 8 warps (2x4),
// warp tile 64x32. K staged 64-wide in SW128-swizzled smem.
// smem: Ah 16K | Al 16K | Bh 16K | Bl 16K  (one stage, 2 syncs per stage);
// epilogue reuses smem as float[128][132] (67584 B dynamic total).
// ---------------------------------------------------------------------------
#define SM_AH 0
#define SM_AL 16384
#define SM_BH 32768
#define SM_BL 49152
#define EPSTR 132
#define GEMM_SMEM (128 * EPSTR * 4)   // 67584

template <int KTOT, int LAYER>
__global__ __launch_bounds__(256)
void gemm_mma(const float* __restrict__ A, float* __restrict__ Cout)
{
    extern __shared__ __align__(1024) char dsm[];

    const __nv_bfloat16* __restrict__ Wh = (LAYER == 1) ? g_W1h : g_W2h;
    const __nv_bfloat16* __restrict__ Wl = (LAYER == 1) ? g_W1l : g_W2l;
    const float* __restrict__ bias       = (LAYER == 1) ? g_b1s : g_b2s;
    float* __restrict__ C                = (LAYER == 1) ? Cout  : g_h2;

    const int tid = threadIdx.x;
    const int wid = tid >> 5;
    const int lid = tid & 31;
    const int wm  = wid & 1;            // 0..1 -> m offset wm*64
    const int wn  = wid >> 1;           // 0..3 -> n offset wn*32
    const int bn  = blockIdx.x;         // n block (0..1)
    const int bm  = blockIdx.y;         // m block

    const uint32_t sb = smem_u32(dsm);
    const float* Abase = A + (size_t)bm * 128 * KTOT;
    const __nv_bfloat16* WhB = Wh + (size_t)bn * 128 * KTOT;
    const __nv_bfloat16* WlB = Wl + (size_t)bn * 128 * KTOT;

    float acc[4][4][4];
#pragma unroll
    for (int i = 0; i < 4; i++)
#pragma unroll
        for (int j = 0; j < 4; j++)
#pragma unroll
            for (int f = 0; f < 4; f++) acc[i][j][f] = 0.f;

    // precomputed ldmatrix lane addressing
    const int lrow = lid & 15;          // row within 16
    const int lkb  = (lid >> 4) * 16;   // 0 or 16 bytes (k half)

    const int NCH = KTOT / 64;
    for (int c = 0; c < NCH; c++) {
        __syncthreads();
        // ---- stage A: 128 rows x 64 k fp32 -> bf16 hi/lo ----
#pragma unroll
        for (int i = 0; i < 4; i++) {
            int u = tid + i * 256;            // 0..1023
            int row = u >> 3, seg = u & 7;    // seg: 8 fp32
            const float4* g = (const float4*)(Abase + (size_t)row * KTOT + c * 64 + seg * 8);
            float4 f0 = g[0], f1 = g[1];
            float v[8] = {f0.x, f0.y, f0.z, f0.w, f1.x, f1.y, f1.z, f1.w};
            uint32_t hi[4], lo[4];
#pragma unroll
            for (int p = 0; p < 4; p++) {
                uint32_t b0 = __float_as_uint(v[2 * p])     & 0xFFFF0000u;
                uint32_t b1 = __float_as_uint(v[2 * p + 1]) & 0xFFFF0000u;
                float l0 = v[2 * p]     - __uint_as_float(b0);
                float l1 = v[2 * p + 1] - __uint_as_float(b1);
                hi[p] = (b0 >> 16) | b1;
                asm("cvt.rn.bf16x2.f32 %0, %1, %2;" : "=r"(lo[p]) : "f"(l1), "f"(l0));
            }
            uint32_t off = sw128((uint32_t)row * 128u + (uint32_t)seg * 16u);
            *(uint4*)(dsm + SM_AH + off) = make_uint4(hi[0], hi[1], hi[2], hi[3]);
            *(uint4*)(dsm + SM_AL + off) = make_uint4(lo[0], lo[1], lo[2], lo[3]);
        }
        // ---- stage B: 128 n-rows x 64 k bf16 hi/lo ----
#pragma unroll
        for (int i = 0; i < 4; i++) {
            int u = tid + i * 256;
            int row = u >> 3, seg = u & 7;
            uint4 vh = *(const uint4*)(WhB + (size_t)row * KTOT + c * 64 + seg * 8);
            uint4 vl = *(const uint4*)(WlB + (size_t)row * KTOT + c * 64 + seg * 8);
            uint32_t off = sw128((uint32_t)row * 128u + (uint32_t)seg * 16u);
            *(uint4*)(dsm + SM_BH + off) = vh;
            *(uint4*)(dsm + SM_BL + off) = vl;
        }
        __syncthreads();

        // ---- compute: 4 k16 steps ----
#pragma unroll
        for (int kk = 0; kk < 4; kk++) {
            uint32_t ah[4][4], al[4][4], bh[4][2], bl[4][2];
#pragma unroll
            for (int mi = 0; mi < 4; mi++) {
                uint32_t row = (uint32_t)(wm * 64 + mi * 16 + lrow);
                uint32_t adr = sw128(row * 128u + (uint32_t)(kk * 32 + lkb));
                LDSM4(ah[mi][0], ah[mi][1], ah[mi][2], ah[mi][3], sb + SM_AH + adr);
                LDSM4(al[mi][0], al[mi][1], al[mi][2], al[mi][3], sb + SM_AL + adr);
            }
#pragma unroll
            for (int nj = 0; nj < 2; nj++) {
                uint32_t row = (uint32_t)(wn * 32 + nj * 16 + lrow);
                uint32_t adr = sw128(row * 128u + (uint32_t)(kk * 32 + lkb));
                uint32_t r0, r1, r2, r3;
                LDSM4(r0, r1, r2, r3, sb + SM_BH + adr);
                bh[2 * nj][0] = r0; bh[2 * nj][1] = r2;
                bh[2 * nj + 1][0] = r1; bh[2 * nj + 1][1] = r3;
                LDSM4(r0, r1, r2, r3, sb + SM_BL + adr);
                bl[2 * nj][0] = r0; bl[2 * nj][1] = r2;
                bl[2 * nj + 1][0] = r1; bl[2 * nj + 1][1] = r3;
            }
#pragma unroll
            for (int mi = 0; mi < 4; mi++)
#pragma unroll
                for (int ni = 0; ni < 4; ni++) {
                    MMA_BF16(acc[mi][ni], ah[mi][0], ah[mi][1], ah[mi][2], ah[mi][3],
                             bh[ni][0], bh[ni][1]);
                    MMA_BF16(acc[mi][ni], al[mi][0], al[mi][1], al[mi][2], al[mi][3],
                             bh[ni][0], bh[ni][1]);
                    MMA_BF16(acc[mi][ni], ah[mi][0], ah[mi][1], ah[mi][2], ah[mi][3],
                             bl[ni][0], bl[ni][1]);
                }
        }
    }

    // ---- epilogue: frags -> smem (transpose) -> bias+relu -> coalesced out ----
    __syncthreads();
    float* Cs = (float*)dsm;
    const int frow = lid >> 2;
    const int fcol = (lid & 3) * 2;
#pragma unroll
    for (int mi = 0; mi < 4; mi++)
#pragma unroll
        for (int ni = 0; ni < 4; ni++) {
            int r0 = wm * 64 + mi * 16 + frow;
            int cc = wn * 32 + ni * 8 + fcol;
            Cs[(size_t)r0 * EPSTR + cc]           = acc[mi][ni][0];
            Cs[(size_t)r0 * EPSTR + cc + 1]       = acc[mi][ni][1];
            Cs[(size_t)(r0 + 8) * EPSTR + cc]     = acc[mi][ni][2];
            Cs[(size_t)(r0 + 8) * EPSTR + cc + 1] = acc[mi][ni][3];
        }
    __syncthreads();
#pragma unroll
    for (int i = 0; i < 16; i++) {
        int idx = tid + i * 256;           // 4096 float4 = 128x128
        int row = idx >> 5, c4 = idx & 31;
        float4 v = *(const float4*)&Cs[(size_t)row * EPSTR + c4 * 4];
        float4 bv = *(const float4*)&bias[bn * 128 + c4 * 4];
        v.x = fmaxf(v.x + bv.x, 0.f);
        v.y = fmaxf(v.y + bv.y, 0.f);
        v.z = fmaxf(v.z + bv.z, 0.f);
        v.w = fmaxf(v.w + bv.w, 0.f);
        *((float4*)(C + (size_t)(bm * 128 + row) * C_OUT + bn * 128) + c4) = v;
    }
}

// ---------------------------------------------------------------------------
// top-3 update (caller guarantees d < d2)
// ---------------------------------------------------------------------------
__device__ __forceinline__ void upd3(float d, int j,
                                     float& d0, float& d1, float& d2,
                                     int& i0, int& i1, int& i2)
{
    if (d < d1) {
        d2 = d1; i2 = i1;
        if (d < d0) { d1 = d0; i1 = i0; d0 = d; i0 = j; }
        else        { d1 = d;  i1 = j; }
    } else { d2 = d; i2 = j; }
}

// ---------------------------------------------------------------------------
// 3-NN: exact d^2 in packed f32x2; 1 query/thread, 128 thr x 512 blocks,
// full 4096-point batch in 48KB SoA smem, 16-point guard groups.
// ---------------------------------------------------------------------------
__global__ __launch_bounds__(128)
void knn_search(const float* __restrict__ p1, const float* __restrict__ p2)
{
    __shared__ float4 sX[KT / 4];
    __shared__ float4 sY[KT / 4];
    __shared__ float4 sZ[KT / 4];

    const int b    = blockIdx.x >> 7;
    const int qblk = blockIdx.x & 127;
    const int tid  = threadIdx.x;

    const float* src = p2 + (size_t)b * KT * 3;
    for (int pt = tid; pt < KT; pt += 128) {
        ((float*)sX)[pt] = src[pt * 3 + 0];
        ((float*)sY)[pt] = src[pt * 3 + 1];
        ((float*)sZ)[pt] = src[pt * 3 + 2];
    }
    __syncthreads();

    const int q = b * N1_PER + qblk * 128 + tid;
    const float qx = p1[q * 3 + 0];
    const float qy = p1[q * 3 + 1];
    const float qz = p1[q * 3 + 2];
    const ull nqx = pack2(-qx, -qx);
    const ull nqy = pack2(-qy, -qy);
    const ull nqz = pack2(-qz, -qz);

    float d0 = 1e30f, d1 = 1e30f, d2 = 1e30f;
    int   i0 = 0,     i1 = 0,     i2 = 0;

    for (int g = 0; g < KT / 16; g++) {
        float r[16];
#pragma unroll
        for (int p = 0; p < 4; p++) {
            float4 fx = sX[g * 4 + p];
            float4 fy = sY[g * 4 + p];
            float4 fz = sZ[g * 4 + p];
            ull dxa = add2(pack2(fx.x, fx.y), nqx);
            ull dya = add2(pack2(fy.x, fy.y), nqy);
            ull dza = add2(pack2(fz.x, fz.y), nqz);
            ull da  = fma2(dza, dza, fma2(dya, dya, mul2(dxa, dxa)));
            ull dxb = add2(pack2(fx.z, fx.w), nqx);
            ull dyb = add2(pack2(fy.z, fy.w), nqy);
            ull dzb = add2(pack2(fz.z, fz.w), nqz);
            ull db  = fma2(dzb, dzb, fma2(dyb, dyb, mul2(dxb, dxb)));
            unpack2(da, r[4 * p + 0], r[4 * p + 1]);
            unpack2(db, r[4 * p + 2], r[4 * p + 3]);
        }
        float m0 = fminf(r[0],  r[1]);
        float m1 = fminf(r[2],  r[3]);
        float m2 = fminf(r[4],  r[5]);
        float m3 = fminf(r[6],  r[7]);
        float m4 = fminf(r[8],  r[9]);
        float m5 = fminf(r[10], r[11]);
        float m6 = fminf(r[12], r[13]);
        float m7 = fminf(r[14], r[15]);
        float m = fminf(fminf(fminf(m0, m1), fminf(m2, m3)),
                        fminf(fminf(m4, m5), fminf(m6, m7)));
        if (m < d2) {
            const int base = g * 16;
#pragma unroll
            for (int cidx = 0; cidx < 16; cidx++)
                if (r[cidx] < d2)
                    upd3(r[cidx], base + cidx, d0, d1, d2, i0, i1, i2);
        }
    }

    float s0 = sqrtf(fmaxf(d0, 1e-12f));
    float s1 = sqrtf(fmaxf(d1, 1e-12f));
    float s2 = sqrtf(fmaxf(d2, 1e-12f));
    float w0 = 1.f / (s0 + 1e-8f);
    float w1 = 1.f / (s1 + 1e-8f);
    float w2 = 1.f / (s2 + 1e-8f);
    float inv = 1.f / (w0 + w1 + w2);

    g_w3[q * 3 + 0] = w0 * inv;
    g_w3[q * 3 + 1] = w1 * inv;
    g_w3[q * 3 + 2] = w2 * inv;
    g_i3[q * 3 + 0] = b * N2_PER + i0;
    g_i3[q * 3 + 1] = b * N2_PER + i1;
    g_i3[q * 3 + 2] = b * N2_PER + i2;
}

// ---------------------------------------------------------------------------
// Gather + accumulate: out[q][:] += sum_k w_k * h2[idx_k][:]
// ---------------------------------------------------------------------------
__global__ __launch_bounds__(256)
void gather_add(float* __restrict__ out)
{
    const int gid = blockIdx.x * 256 + threadIdx.x;
    const int q   = gid >> 6;
    const int c4  = gid & 63;

    float w0 = g_w3[q * 3 + 0];
    float w1 = g_w3[q * 3 + 1];
    float w2 = g_w3[q * 3 + 2];
    int   r0 = g_i3[q * 3 + 0];
    int   r1 = g_i3[q * 3 + 1];
    int   r2 = g_i3[q * 3 + 2];

    float4 f0 = *(const float4*)(g_h2 + (size_t)r0 * C_OUT + c4 * 4);
    float4 f1 = *(const float4*)(g_h2 + (size_t)r1 * C_OUT + c4 * 4);
    float4 f2 = *(const float4*)(g_h2 + (size_t)r2 * C_OUT + c4 * 4);

    float4* op = (float4*)out + (size_t)q * 64 + c4;
    float4 o = *op;
    o.x += w0 * f0.x + w1 * f1.x + w2 * f2.x;
    o.y += w0 * f0.y + w1 * f1.y + w2 * f2.y;
    o.z += w0 * f0.z + w1 * f1.z + w2 * f2.z;
    o.w += w0 * f0.w + w1 * f1.w + w2 * f2.w;
    *op = o;
}

// ---------------------------------------------------------------------------
extern "C" void kernel_launch(void* const* d_in, const int* in_sizes, int n_in,
                              void* d_out, int out_size)
{
    const float* p1 = (const float*)d_in[0];
    const float* x1 = (const float*)d_in[1];
    const float* p2 = (const float*)d_in[2];
    const float* x2 = (const float*)d_in[3];

    static int attr_done = 0;
    if (!attr_done) {
        cudaFuncSetAttribute(gemm_mma<C_OUT, 1>,
                             cudaFuncAttributeMaxDynamicSharedMemorySize, GEMM_SMEM);
        cudaFuncSetAttribute(gemm_mma<C_IN, 2>,
                             cudaFuncAttributeMaxDynamicSharedMemorySize, GEMM_SMEM);
        attr_done = 1;
    }

    prep_weights<<<C_OUT, 256>>>((const float*)d_in[4],  (const float*)d_in[5],
                                 (const float*)d_in[6],  (const float*)d_in[7],
                                 (const float*)d_in[8],  (const float*)d_in[9],
                                 (const float*)d_in[10], (const float*)d_in[11],
                                 (const float*)d_in[12], (const float*)d_in[13],
                                 (const float*)d_in[14], (const float*)d_in[15]);

    {   // h2 = relu(bn(x2 @ W2^T)) -> g_h2
        dim3 grid(C_OUT / 128, N2_TOT / 128);
        gemm_mma<C_IN, 2><<<grid, 256, GEMM_SMEM>>>(x2, nullptr);
    }
    {   // h1 = relu(bn(x1 @ W1^T)) -> d_out
        dim3 grid(C_OUT / 128, N1_TOT / 128);
        gemm_mma<C_OUT, 1><<<grid, 256, GEMM_SMEM>>>(x1, (float*)d_out);
    }
    knn_search<<<BATCH * (N1_PER / 128), 128>>>(p1, p2);
    gather_add<<<(N1_TOT * 64) / 256, 256>>>((float*)d_out);
}